// round 12
// baseline (speedup 1.0000x reference)
#include <cuda_runtime.h>

#define TT 64
#define BB 256
#define DD 512

// pre-activations, K2-block-contiguous layout:
// g_pre2[bblk(32)][t(64)][bloc(8)][gate(4)][q(6)]
__device__ __align__(16) float g_pre2[TT * BB * 24];

// ---------------------------------------------------------------------------
// K1: pre[t,b,g,q] = inputs[t,b,:] @ Wg[:512,q] + bg[q] + theta_g[q]
// EXACT R2 kernel (best measured K1). grid 128 x 256.
// ---------------------------------------------------------------------------
__global__ void __launch_bounds__(256, 1) k1_gemm(
    const float* __restrict__ X,
    const float* __restrict__ Wf, const float* __restrict__ bf,
    const float* __restrict__ Wi, const float* __restrict__ bi,
    const float* __restrict__ Wu, const float* __restrict__ bu,
    const float* __restrict__ Wo, const float* __restrict__ bo,
    const float* __restrict__ thf, const float* __restrict__ thi,
    const float* __restrict__ thu, const float* __restrict__ tho)
{
    __shared__ float Wph[256 * 24];   // K-half of W, [dd][g*6+q]
    __shared__ float Xsh[32 * 130];   // x tile transposed [d][row]

    const int tid  = threadIdx.x;
    const int warp = tid >> 5;
    const int lane = tid & 31;
    const int gate = warp & 3;
    const int rloc = ((warp >> 2) << 6) + (lane << 1);   // block-local row (even)
    const int rowbase = blockIdx.x << 7;

    const float* bg = (gate == 0) ? bf  : (gate == 1) ? bi  : (gate == 2) ? bu  : bo;
    const float* tg = (gate == 0) ? thf : (gate == 1) ? thi : (gate == 2) ? thu : tho;

    unsigned long long a0[3], a1[3];
#pragma unroll
    for (int p = 0; p < 3; p++) {
        float blo = __ldg(bg + 2 * p + 0) + __ldg(tg + 2 * p + 0);
        float bhi = __ldg(bg + 2 * p + 1) + __ldg(tg + 2 * p + 1);
        unsigned long long bp;
        asm("mov.b64 %0, {%1, %2};" : "=l"(bp) : "f"(blo), "f"(bhi));
        a0[p] = bp;
        a1[p] = bp;
    }

    const int cc = tid & 7;   // d-group for staging
    const int rr = tid >> 3;  // row for staging

    for (int kh = 0; kh < 2; kh++) {
        __syncthreads();
#pragma unroll
        for (int k = 0; k < 24; k++) {
            int idx = tid + (k << 8);          // dd*24 + col
            int dd  = idx / 24;
            int col = idx - dd * 24;
            int g2  = col / 6;
            int q2  = col - g2 * 6;
            const float* Ws = (g2 == 0) ? Wf : (g2 == 1) ? Wi : (g2 == 2) ? Wu : Wo;
            Wph[idx] = Ws[((kh << 8) + dd) * 6 + q2];
        }
        for (int tile = 0; tile < 8; tile++) {
            const int d0 = (kh << 8) + (tile << 5);
            __syncthreads();
#pragma unroll
            for (int p = 0; p < 4; p++) {
                int r = rr + (p << 5);
                const float4 v = *reinterpret_cast<const float4*>(
                    X + (size_t)(rowbase + r) * DD + d0 + (cc << 2));
                Xsh[((cc << 2) + 0) * 130 + r] = v.x;
                Xsh[((cc << 2) + 1) * 130 + r] = v.y;
                Xsh[((cc << 2) + 2) * 130 + r] = v.z;
                Xsh[((cc << 2) + 3) * 130 + r] = v.w;
            }
            __syncthreads();
#pragma unroll
            for (int d = 0; d < 32; d++) {
                const int dd = (tile << 5) + d;
                const unsigned long long* wp =
                    reinterpret_cast<const unsigned long long*>(&Wph[dd * 24 + gate * 6]);
                const unsigned long long w01 = wp[0];
                const unsigned long long w23 = wp[1];
                const unsigned long long w45 = wp[2];
                const float2 x2 = *reinterpret_cast<const float2*>(&Xsh[d * 130 + rloc]);
                unsigned long long xr0, xr1;
                asm("mov.b64 %0, {%1, %1};" : "=l"(xr0) : "f"(x2.x));
                asm("mov.b64 %0, {%1, %1};" : "=l"(xr1) : "f"(x2.y));
                asm("fma.rn.f32x2 %0, %1, %2, %0;" : "+l"(a0[0]) : "l"(w01), "l"(xr0));
                asm("fma.rn.f32x2 %0, %1, %2, %0;" : "+l"(a0[1]) : "l"(w23), "l"(xr0));
                asm("fma.rn.f32x2 %0, %1, %2, %0;" : "+l"(a0[2]) : "l"(w45), "l"(xr0));
                asm("fma.rn.f32x2 %0, %1, %2, %0;" : "+l"(a1[0]) : "l"(w01), "l"(xr1));
                asm("fma.rn.f32x2 %0, %1, %2, %0;" : "+l"(a1[1]) : "l"(w23), "l"(xr1));
                asm("fma.rn.f32x2 %0, %1, %2, %0;" : "+l"(a1[2]) : "l"(w45), "l"(xr1));
            }
        }
    }

    const int t = rowbase >> 8;
    const int b = (rowbase & 255) + rloc;       // even; b+1 shares b>>3
    float* dst = g_pre2 + ((size_t)((b >> 3) * 64 + t) * 192) + (b & 7) * 24 + gate * 6;
    unsigned long long* d64 = reinterpret_cast<unsigned long long*>(dst);
    d64[0] = a0[0]; d64[1] = a0[1]; d64[2] = a0[2];
    unsigned long long* e64 = reinterpret_cast<unsigned long long*>(dst + 24);
    e64[0] = a1[0]; e64[1] = a1[1]; e64[2] = a1[2];
}

// tanh via CF rational, one rcp; err <= ~2e-5 for |x| <= 2.2 (|c| <= 2.08).
__device__ __forceinline__ float tanh_rat(float x) {
    float s = x * x;
    float num = fmaf(s, fmaf(s, 21.0f, 1260.0f), 10395.0f);
    float den = fmaf(s, fmaf(s, s + 210.0f, 4725.0f), 10395.0f);
    float r;
    asm("rcp.approx.f32 %0, %1;" : "=f"(r) : "f"(den));
    return x * num * r;
}

// ---------------------------------------------------------------------------
// K2: LSTM scan, wire-split + DUAL-STREAM. grid 32 x 128; all threads stage
// 48KB; warp 0 scans ALL 8 batches: each lane runs two independent streams
// (batch bl and bl+4) interleaved to hide the per-stream dependency chain.
// lane = bl*8 + gate*2 + qh; each lane owns 3 wires (q = 3qh..3qh+2).
// ---------------------------------------------------------------------------
__global__ void __launch_bounds__(128, 1) k2_scan(
    const float* __restrict__ Wf, const float* __restrict__ Wi,
    const float* __restrict__ Wu, const float* __restrict__ Wo,
    float* __restrict__ out)
{
    __shared__ float ps[TT * 192];    // 48KB : [t][bloc(8)][gate][q]

    const int tid = threadIdx.x;

    {
        const float4* src = reinterpret_cast<const float4*>(g_pre2 + (size_t)blockIdx.x * (TT * 192));
        float4* dst = reinterpret_cast<float4*>(ps);
#pragma unroll
        for (int i = 0; i < (TT * 192) / 4 / 128; i++)
            dst[tid + i * 128] = src[tid + i * 128];
    }
    __syncthreads();
    if (tid >= 32) return;

    const int lane = tid;
    const int qh   = lane & 1;            // wire half
    const int g    = (lane >> 1) & 3;     // gate
    const int bl   = lane >> 3;           // batch within warp (0..3)
    const int bA   = (blockIdx.x << 3) + bl;        // stream A batch
    const int bB   = bA + 4;                        // stream B batch
    const int q0   = 3 * qh;
    const float* Wg = (g == 0) ? Wf : (g == 1) ? Wi : (g == 2) ? Wu : Wo;

    // recurrent weights for own 3 wires: Whk[k][j] = Wg[512+k][q0+j]
    float Whk[6][3];
#pragma unroll
    for (int k = 0; k < 6; k++)
#pragma unroll
        for (int j = 0; j < 3; j++)
            Whk[k][j] = __ldg(Wg + (DD + k) * 6 + q0 + j);

    float hA[6], hB[6];
#pragma unroll
    for (int k = 0; k < 6; k++) { hA[k] = 0.0f; hB[k] = 0.0f; }
    float cA[3] = { 0.0f, 0.0f, 0.0f };
    float cB[3] = { 0.0f, 0.0f, 0.0f };

    const float* pbA = ps + bl * 24 + g * 6 + q0;
    const float* pbB = pbA + 96;                    // +4 batches
    const unsigned mask = 0xffffffffu;
    const int lb  = (lane & 24) | qh;     // gate-0 lane of this (batch, qh)
    const bool isU = (g == 2);
    const float cmul = isU ? -2.0f : -1.0f;
    const bool store = (g == 0);

#pragma unroll 1
    for (int t = 0; t < TT; t++) {
        // ---- phase 1: dot (both streams) ----
        float aA[3], aB[3];
#pragma unroll
        for (int j = 0; j < 3; j++) {
            float u0 = fmaf(hA[2], Whk[2][j], fmaf(hA[1], Whk[1][j], fmaf(hA[0], Whk[0][j], pbA[t * 192 + j])));
            float u1 = fmaf(hA[3], Whk[3][j], fmaf(hA[4], Whk[4][j], hA[5] * Whk[5][j]));
            aA[j] = u0 + u1;
        }
#pragma unroll
        for (int j = 0; j < 3; j++) {
            float u0 = fmaf(hB[2], Whk[2][j], fmaf(hB[1], Whk[1][j], fmaf(hB[0], Whk[0][j], pbB[t * 192 + j])));
            float u1 = fmaf(hB[3], Whk[3][j], fmaf(hB[4], Whk[4][j], hB[5] * Whk[5][j]));
            aB[j] = u0 + u1;
        }

        // ---- phase 2: cos ----
        float zA0 = __cosf(aA[0]), zA1 = __cosf(aA[1]), zA2 = __cosf(aA[2]);
        float zB0 = __cosf(aB[0]), zB1 = __cosf(aB[1]), zB2 = __cosf(aB[2]);

        // ---- phase 3: partner z exchange (both streams) ----
        float zAp0 = __shfl_xor_sync(mask, zA0, 1);
        float zAp1 = __shfl_xor_sync(mask, zA1, 1);
        float zAp2 = __shfl_xor_sync(mask, zA2, 1);
        float zBp0 = __shfl_xor_sync(mask, zB0, 1);
        float zBp1 = __shfl_xor_sync(mask, zB1, 1);
        float zBp2 = __shfl_xor_sync(mask, zB2, 1);

        float wvA0, wvA1, wvA2, wvB0, wvB1, wvB2;
        {
            float y0 = qh ? zAp0 : zA0;   // q0
            float y1 = qh ? zAp1 : zA1;   // q1
            float y2 = qh ? zAp2 : zA2;   // q2
            float y3 = qh ? zA0 : zAp0;   // q3
            float y4 = qh ? zA1 : zAp1;   // q4
            float y5 = qh ? zA2 : zAp2;   // q5
            float z01 = y0 * y1, z23 = y2 * y3, z45 = y4 * y5;
            float w3  = z01 * z23;
            wvA0 = qh ? w3       : y1 * (z23 * z45);
            wvA1 = qh ? w3 * y4  : z01;
            wvA2 = qh ? w3 * z45 : z01 * y2;
        }
        {
            float y0 = qh ? zBp0 : zB0;
            float y1 = qh ? zBp1 : zB1;
            float y2 = qh ? zBp2 : zB2;
            float y3 = qh ? zB0 : zBp0;
            float y4 = qh ? zB1 : zBp1;
            float y5 = qh ? zB2 : zBp2;
            float z01 = y0 * y1, z23 = y2 * y3, z45 = y4 * y5;
            float w3  = z01 * z23;
            wvB0 = qh ? w3       : y1 * (z23 * z45);
            wvB1 = qh ? w3 * y4  : z01;
            wvB2 = qh ? w3 * z45 : z01 * y2;
        }

        // ---- phase 4: gate values (exp-based), both streams ----
        float vA0, vA1, vA2, vB0, vB1, vB2;
        {
            float e0 = __expf(cmul * wvA0);
            float e1 = __expf(cmul * wvA1);
            float e2 = __expf(cmul * wvA2);
            float e3 = __expf(cmul * wvB0);
            float e4 = __expf(cmul * wvB1);
            float e5 = __expf(cmul * wvB2);
            float s0 = __fdividef(1.0f, 1.0f + e0);
            float s1 = __fdividef(1.0f, 1.0f + e1);
            float s2 = __fdividef(1.0f, 1.0f + e2);
            float s3 = __fdividef(1.0f, 1.0f + e3);
            float s4 = __fdividef(1.0f, 1.0f + e4);
            float s5 = __fdividef(1.0f, 1.0f + e5);
            vA0 = isU ? fmaf(2.0f, s0, -1.0f) : s0;
            vA1 = isU ? fmaf(2.0f, s1, -1.0f) : s1;
            vA2 = isU ? fmaf(2.0f, s2, -1.0f) : s2;
            vB0 = isU ? fmaf(2.0f, s3, -1.0f) : s3;
            vB1 = isU ? fmaf(2.0f, s4, -1.0f) : s4;
            vB2 = isU ? fmaf(2.0f, s5, -1.0f) : s5;
        }

        // ---- phase 5+6: gate gather + c/h update, both streams ----
        float hqA[3], hqB[3];
#pragma unroll
        for (int j = 0; j < 3; j++) {
            float vj = (j == 0) ? vA0 : (j == 1) ? vA1 : vA2;
            float fq = __shfl_sync(mask, vj, lb + 0);
            float iq = __shfl_sync(mask, vj, lb + 2);
            float uq = __shfl_sync(mask, vj, lb + 4);
            float oq = __shfl_sync(mask, vj, lb + 6);
            float cn = fmaf(fq, cA[j], iq * uq);
            cA[j] = cn;
            hqA[j] = oq * tanh_rat(cn);
        }
#pragma unroll
        for (int j = 0; j < 3; j++) {
            float vj = (j == 0) ? vB0 : (j == 1) ? vB1 : vB2;
            float fq = __shfl_sync(mask, vj, lb + 0);
            float iq = __shfl_sync(mask, vj, lb + 2);
            float uq = __shfl_sync(mask, vj, lb + 4);
            float oq = __shfl_sync(mask, vj, lb + 6);
            float cn = fmaf(fq, cB[j], iq * uq);
            cB[j] = cn;
            hqB[j] = oq * tanh_rat(cn);
        }

        if (store) {
            float* oA = out + ((size_t)t * BB + bA) * 6 + q0;
            oA[0] = hqA[0]; oA[1] = hqA[1]; oA[2] = hqA[2];
            float* oB = out + ((size_t)t * BB + bB) * 6 + q0;
            oB[0] = hqB[0]; oB[1] = hqB[1]; oB[2] = hqB[2];
        }

        // ---- phase 7: h exchange + rebuild (both streams) ----
        float hpA0 = __shfl_xor_sync(mask, hqA[0], 1);
        float hpA1 = __shfl_xor_sync(mask, hqA[1], 1);
        float hpA2 = __shfl_xor_sync(mask, hqA[2], 1);
        float hpB0 = __shfl_xor_sync(mask, hqB[0], 1);
        float hpB1 = __shfl_xor_sync(mask, hqB[1], 1);
        float hpB2 = __shfl_xor_sync(mask, hqB[2], 1);
        hA[0] = qh ? hpA0 : hqA[0];
        hA[1] = qh ? hpA1 : hqA[1];
        hA[2] = qh ? hpA2 : hqA[2];
        hA[3] = qh ? hqA[0] : hpA0;
        hA[4] = qh ? hqA[1] : hpA1;
        hA[5] = qh ? hqA[2] : hpA2;
        hB[0] = qh ? hpB0 : hqB[0];
        hB[1] = qh ? hpB1 : hqB[1];
        hB[2] = qh ? hpB2 : hqB[2];
        hB[3] = qh ? hqB[0] : hpB0;
        hB[4] = qh ? hqB[1] : hpB1;
        hB[5] = qh ? hqB[2] : hpB2;
    }

    if (store) {
        float* hxA = out + (size_t)TT * BB * 6 + (size_t)bA * 6 + q0;
        float* cxA = hxA + BB * 6;
        hxA[0] = qh ? hA[3] : hA[0];
        hxA[1] = qh ? hA[4] : hA[1];
        hxA[2] = qh ? hA[5] : hA[2];
        cxA[0] = cA[0]; cxA[1] = cA[1]; cxA[2] = cA[2];
        float* hxB = out + (size_t)TT * BB * 6 + (size_t)bB * 6 + q0;
        float* cxB = hxB + BB * 6;
        hxB[0] = qh ? hB[3] : hB[0];
        hxB[1] = qh ? hB[4] : hB[1];
        hxB[2] = qh ? hB[5] : hB[2];
        cxB[0] = cB[0]; cxB[1] = cB[1]; cxB[2] = cB[2];
    }
}

extern "C" void kernel_launch(void* const* d_in, const int* in_sizes, int n_in,
                              void* d_out, int out_size)
{
    const float* X   = (const float*)d_in[0];
    const float* Wf  = (const float*)d_in[1];
    const float* bf  = (const float*)d_in[2];
    const float* Wi  = (const float*)d_in[3];
    const float* bi  = (const float*)d_in[4];
    const float* Wu  = (const float*)d_in[5];
    const float* bu  = (const float*)d_in[6];
    const float* Wo  = (const float*)d_in[7];
    const float* bo  = (const float*)d_in[8];
    const float* thf = (const float*)d_in[9];
    const float* thi = (const float*)d_in[10];
    const float* thu = (const float*)d_in[11];
    const float* tho = (const float*)d_in[12];
    float* out = (float*)d_out;

    k1_gemm<<<128, 256>>>(X, Wf, bf, Wi, bi, Wu, bu, Wo, bo, thf, thi, thu, tho);
    k2_scan<<<32, 128>>>(Wf, Wi, Wu, Wo, out);
}

// round 13
// speedup vs baseline: 1.0478x; 1.0478x over previous
#include <cuda_runtime.h>

#define TT 64
#define BB 256
#define DD 512

// pre-activations, K2-block-contiguous layout:
// g_pre2[bblk(32)][t(64)][bloc(8)][gate(4)][q(6)]
__device__ __align__(16) float g_pre2[TT * BB * 24];

// ---------------------------------------------------------------------------
// K1: pre[t,b,g,q] = inputs[t,b,:] @ Wg[:512,q] + bg[q] + theta_g[q]
// EXACT R2 kernel (best measured K1). grid 128 x 256.
// ---------------------------------------------------------------------------
__global__ void __launch_bounds__(256, 1) k1_gemm(
    const float* __restrict__ X,
    const float* __restrict__ Wf, const float* __restrict__ bf,
    const float* __restrict__ Wi, const float* __restrict__ bi,
    const float* __restrict__ Wu, const float* __restrict__ bu,
    const float* __restrict__ Wo, const float* __restrict__ bo,
    const float* __restrict__ thf, const float* __restrict__ thi,
    const float* __restrict__ thu, const float* __restrict__ tho)
{
    __shared__ float Wph[256 * 24];   // K-half of W, [dd][g*6+q]
    __shared__ float Xsh[32 * 130];   // x tile transposed [d][row]

    const int tid  = threadIdx.x;
    const int warp = tid >> 5;
    const int lane = tid & 31;
    const int gate = warp & 3;
    const int rloc = ((warp >> 2) << 6) + (lane << 1);   // block-local row (even)
    const int rowbase = blockIdx.x << 7;

    const float* bg = (gate == 0) ? bf  : (gate == 1) ? bi  : (gate == 2) ? bu  : bo;
    const float* tg = (gate == 0) ? thf : (gate == 1) ? thi : (gate == 2) ? thu : tho;

    unsigned long long a0[3], a1[3];
#pragma unroll
    for (int p = 0; p < 3; p++) {
        float blo = __ldg(bg + 2 * p + 0) + __ldg(tg + 2 * p + 0);
        float bhi = __ldg(bg + 2 * p + 1) + __ldg(tg + 2 * p + 1);
        unsigned long long bp;
        asm("mov.b64 %0, {%1, %2};" : "=l"(bp) : "f"(blo), "f"(bhi));
        a0[p] = bp;
        a1[p] = bp;
    }

    const int cc = tid & 7;   // d-group for staging
    const int rr = tid >> 3;  // row for staging

    for (int kh = 0; kh < 2; kh++) {
        __syncthreads();
#pragma unroll
        for (int k = 0; k < 24; k++) {
            int idx = tid + (k << 8);          // dd*24 + col
            int dd  = idx / 24;
            int col = idx - dd * 24;
            int g2  = col / 6;
            int q2  = col - g2 * 6;
            const float* Ws = (g2 == 0) ? Wf : (g2 == 1) ? Wi : (g2 == 2) ? Wu : Wo;
            Wph[idx] = Ws[((kh << 8) + dd) * 6 + q2];
        }
        for (int tile = 0; tile < 8; tile++) {
            const int d0 = (kh << 8) + (tile << 5);
            __syncthreads();
#pragma unroll
            for (int p = 0; p < 4; p++) {
                int r = rr + (p << 5);
                const float4 v = *reinterpret_cast<const float4*>(
                    X + (size_t)(rowbase + r) * DD + d0 + (cc << 2));
                Xsh[((cc << 2) + 0) * 130 + r] = v.x;
                Xsh[((cc << 2) + 1) * 130 + r] = v.y;
                Xsh[((cc << 2) + 2) * 130 + r] = v.z;
                Xsh[((cc << 2) + 3) * 130 + r] = v.w;
            }
            __syncthreads();
#pragma unroll
            for (int d = 0; d < 32; d++) {
                const int dd = (tile << 5) + d;
                const unsigned long long* wp =
                    reinterpret_cast<const unsigned long long*>(&Wph[dd * 24 + gate * 6]);
                const unsigned long long w01 = wp[0];
                const unsigned long long w23 = wp[1];
                const unsigned long long w45 = wp[2];
                const float2 x2 = *reinterpret_cast<const float2*>(&Xsh[d * 130 + rloc]);
                unsigned long long xr0, xr1;
                asm("mov.b64 %0, {%1, %1};" : "=l"(xr0) : "f"(x2.x));
                asm("mov.b64 %0, {%1, %1};" : "=l"(xr1) : "f"(x2.y));
                asm("fma.rn.f32x2 %0, %1, %2, %0;" : "+l"(a0[0]) : "l"(w01), "l"(xr0));
                asm("fma.rn.f32x2 %0, %1, %2, %0;" : "+l"(a0[1]) : "l"(w23), "l"(xr0));
                asm("fma.rn.f32x2 %0, %1, %2, %0;" : "+l"(a0[2]) : "l"(w45), "l"(xr0));
                asm("fma.rn.f32x2 %0, %1, %2, %0;" : "+l"(a1[0]) : "l"(w01), "l"(xr1));
                asm("fma.rn.f32x2 %0, %1, %2, %0;" : "+l"(a1[1]) : "l"(w23), "l"(xr1));
                asm("fma.rn.f32x2 %0, %1, %2, %0;" : "+l"(a1[2]) : "l"(w45), "l"(xr1));
            }
        }
    }

    const int t = rowbase >> 8;
    const int b = (rowbase & 255) + rloc;       // even; b+1 shares b>>3
    float* dst = g_pre2 + ((size_t)((b >> 3) * 64 + t) * 192) + (b & 7) * 24 + gate * 6;
    unsigned long long* d64 = reinterpret_cast<unsigned long long*>(dst);
    d64[0] = a0[0]; d64[1] = a0[1]; d64[2] = a0[2];
    unsigned long long* e64 = reinterpret_cast<unsigned long long*>(dst + 24);
    e64[0] = a1[0]; e64[1] = a1[1]; e64[2] = a1[2];
}

// tanh via CF rational, one rcp; err <= ~2e-5 for |x| <= 2.2 (|c| <= 2.08).
__device__ __forceinline__ float tanh_rat(float x) {
    float s = x * x;
    float num = fmaf(s, fmaf(s, 21.0f, 1260.0f), 10395.0f);
    float den = fmaf(s, fmaf(s, s + 210.0f, 4725.0f), 10395.0f);
    float r;
    asm("rcp.approx.f32 %0, %1;" : "=f"(r) : "f"(den));
    return x * num * r;
}

// ---------------------------------------------------------------------------
// K2: LSTM scan — EXACT R11 kernel (best measured: 17.2us).
// Wire-split, 2 scan warps x 4 batches. lane = bl*8 + gate*2 + qh.
// ---------------------------------------------------------------------------
__global__ void __launch_bounds__(128, 1) k2_scan(
    const float* __restrict__ Wf, const float* __restrict__ Wi,
    const float* __restrict__ Wu, const float* __restrict__ Wo,
    float* __restrict__ out)
{
    __shared__ float ps[TT * 192];    // 48KB : [t][bloc(8)][gate][q]

    const int tid = threadIdx.x;

    {
        const float4* src = reinterpret_cast<const float4*>(g_pre2 + (size_t)blockIdx.x * (TT * 192));
        float4* dst = reinterpret_cast<float4*>(ps);
#pragma unroll
        for (int i = 0; i < (TT * 192) / 4 / 128; i++)
            dst[tid + i * 128] = src[tid + i * 128];
    }
    __syncthreads();
    if (tid >= 64) return;

    const int lane = tid & 31;
    const int wrp  = tid >> 5;            // 0 or 1
    const int qh   = lane & 1;            // wire half
    const int g    = (lane >> 1) & 3;     // gate
    const int bl   = lane >> 3;           // batch within warp (0..3)
    const int bloc = (wrp << 2) + bl;     // batch within block (0..7)
    const int b    = (blockIdx.x << 3) + bloc;
    const int q0   = 3 * qh;
    const float* Wg = (g == 0) ? Wf : (g == 1) ? Wi : (g == 2) ? Wu : Wo;

    float Whk[6][3];
#pragma unroll
    for (int k = 0; k < 6; k++)
#pragma unroll
        for (int j = 0; j < 3; j++)
            Whk[k][j] = __ldg(Wg + (DD + k) * 6 + q0 + j);

    float h6[6];
#pragma unroll
    for (int k = 0; k < 6; k++) h6[k] = 0.0f;
    float c[3] = { 0.0f, 0.0f, 0.0f };

    const float* pb = ps + bloc * 24 + g * 6 + q0;
    const unsigned mask = 0xffffffffu;
    const int lb  = (lane & 24) | qh;     // gate-0 lane of this (batch, qh)
    const bool isU = (g == 2);
    const float cmul = isU ? -2.0f : -1.0f;
    const bool store = (g == 0);

#pragma unroll 2
    for (int t = 0; t < TT; t++) {
        const float p0 = pb[t * 192 + 0];
        const float p1 = pb[t * 192 + 1];
        const float p2 = pb[t * 192 + 2];

        float a[3];
        {
            float pj[3] = { p0, p1, p2 };
#pragma unroll
            for (int j = 0; j < 3; j++) {
                float u0 = fmaf(h6[0], Whk[0][j], fmaf(h6[1], Whk[1][j], fmaf(h6[2], Whk[2][j], pj[j])));
                float u1 = fmaf(h6[3], Whk[3][j], fmaf(h6[4], Whk[4][j], h6[5] * Whk[5][j]));
                a[j] = u0 + u1;
            }
        }

        float z0 = __cosf(a[0]);
        float z1 = __cosf(a[1]);
        float z2 = __cosf(a[2]);

        float zp0 = __shfl_xor_sync(mask, z0, 1);
        float zp1 = __shfl_xor_sync(mask, z1, 1);
        float zp2 = __shfl_xor_sync(mask, z2, 1);
        float zA0 = qh ? zp0 : z0;   // q0
        float zA1 = qh ? zp1 : z1;   // q1
        float zA2 = qh ? zp2 : z2;   // q2
        float zB0 = qh ? z0 : zp0;   // q3
        float zB1 = qh ? z1 : zp1;   // q4
        float zB2 = qh ? z2 : zp2;   // q5

        float z01 = zA0 * zA1;
        float z23 = zA2 * zB0;
        float z45 = zB1 * zB2;
        float w3  = z01 * z23;
        float wv0 = qh ? w3        : zA1 * (z23 * z45);   // w3 : w0
        float wv1 = qh ? w3 * zB1  : z01;                 // w4 : w1
        float wv2 = qh ? w3 * z45  : z01 * zA2;           // w5 : w2

        float v0, v1, v2;
        {
            float e0 = __expf(cmul * wv0);
            float e1 = __expf(cmul * wv1);
            float e2 = __expf(cmul * wv2);
            float s0 = __fdividef(1.0f, 1.0f + e0);
            float s1 = __fdividef(1.0f, 1.0f + e1);
            float s2 = __fdividef(1.0f, 1.0f + e2);
            v0 = isU ? fmaf(2.0f, s0, -1.0f) : s0;
            v1 = isU ? fmaf(2.0f, s1, -1.0f) : s1;
            v2 = isU ? fmaf(2.0f, s2, -1.0f) : s2;
        }

        float hq[3];
#pragma unroll
        for (int j = 0; j < 3; j++) {
            float vj = (j == 0) ? v0 : (j == 1) ? v1 : v2;
            float fq = __shfl_sync(mask, vj, lb + 0);
            float iq = __shfl_sync(mask, vj, lb + 2);
            float uq = __shfl_sync(mask, vj, lb + 4);
            float oq = __shfl_sync(mask, vj, lb + 6);
            float cn = fmaf(fq, c[j], iq * uq);
            c[j] = cn;
            hq[j] = oq * tanh_rat(cn);     // |cn| <= 2.08 guaranteed
        }

        if (store) {
            float* o0 = out + ((size_t)t * BB + b) * 6 + q0;
            o0[0] = hq[0]; o0[1] = hq[1]; o0[2] = hq[2];
        }

        float hp0 = __shfl_xor_sync(mask, hq[0], 1);
        float hp1 = __shfl_xor_sync(mask, hq[1], 1);
        float hp2 = __shfl_xor_sync(mask, hq[2], 1);
        h6[0] = qh ? hp0 : hq[0];
        h6[1] = qh ? hp1 : hq[1];
        h6[2] = qh ? hp2 : hq[2];
        h6[3] = qh ? hq[0] : hp0;
        h6[4] = qh ? hq[1] : hp1;
        h6[5] = qh ? hq[2] : hp2;
    }

    if (store) {
        float* hx = out + (size_t)TT * BB * 6 + (size_t)b * 6 + q0;
        float* cx = hx + BB * 6;
        hx[0] = qh ? h6[3] : h6[0];
        hx[1] = qh ? h6[4] : h6[1];
        hx[2] = qh ? h6[5] : h6[2];
        cx[0] = c[0]; cx[1] = c[1]; cx[2] = c[2];
    }
}

// Diagnostic no-op: shifts ncu's "-s 5 -c 1" capture window onto k1_gemm
// (launch cycle becomes k1,k2,d,d,d -> launch #6 is k1). Deterministic, does
// no memory work.
__global__ void k_nop() {}

extern "C" void kernel_launch(void* const* d_in, const int* in_sizes, int n_in,
                              void* d_out, int out_size)
{
    const float* X   = (const float*)d_in[0];
    const float* Wf  = (const float*)d_in[1];
    const float* bf  = (const float*)d_in[2];
    const float* Wi  = (const float*)d_in[3];
    const float* bi  = (const float*)d_in[4];
    const float* Wu  = (const float*)d_in[5];
    const float* bu  = (const float*)d_in[6];
    const float* Wo  = (const float*)d_in[7];
    const float* bo  = (const float*)d_in[8];
    const float* thf = (const float*)d_in[9];
    const float* thi = (const float*)d_in[10];
    const float* thu = (const float*)d_in[11];
    const float* tho = (const float*)d_in[12];
    float* out = (float*)d_out;

    k1_gemm<<<128, 256>>>(X, Wf, bf, Wi, bi, Wu, bu, Wo, bo, thf, thi, thu, tho);
    k2_scan<<<32, 128>>>(Wf, Wi, Wu, Wo, out);
    k_nop<<<1, 1>>>();
    k_nop<<<1, 1>>>();
    k_nop<<<1, 1>>>();
}

// round 14
// speedup vs baseline: 1.1619x; 1.1090x over previous
#include <cuda_runtime.h>

#define TT 64
#define BB 256
#define DD 512

// pre-activations, K2-block-contiguous layout:
// g_pre2[bblk(32)][t(64)][bloc(8)][gate(4)][q(6)]
__device__ __align__(16) float g_pre2[TT * BB * 24];

// ---------------------------------------------------------------------------
// K1: pre[t,b,g,q] = inputs[t,b,:] @ Wg[:512,q] + bg[q] + theta_g[q]
// R2 kernel + X-tile software pipelining: tile t+1's LDGs issue before tile
// t's compute, so the per-tile LDG->STS latency is hidden behind ~704 cyc of
// FFMA2. Layouts, transpose, sync structure otherwise identical to R2.
// ---------------------------------------------------------------------------
__global__ void __launch_bounds__(256, 1) k1_gemm(
    const float* __restrict__ X,
    const float* __restrict__ Wf, const float* __restrict__ bf,
    const float* __restrict__ Wi, const float* __restrict__ bi,
    const float* __restrict__ Wu, const float* __restrict__ bu,
    const float* __restrict__ Wo, const float* __restrict__ bo,
    const float* __restrict__ thf, const float* __restrict__ thi,
    const float* __restrict__ thu, const float* __restrict__ tho)
{
    __shared__ float Wph[256 * 24];   // K-half of W, [dd][g*6+q]
    __shared__ float Xsh[32 * 130];   // x tile transposed [d][row]

    const int tid  = threadIdx.x;
    const int warp = tid >> 5;
    const int lane = tid & 31;
    const int gate = warp & 3;
    const int rloc = ((warp >> 2) << 6) + (lane << 1);   // block-local row (even)
    const int rowbase = blockIdx.x << 7;

    const float* bg = (gate == 0) ? bf  : (gate == 1) ? bi  : (gate == 2) ? bu  : bo;
    const float* tg = (gate == 0) ? thf : (gate == 1) ? thi : (gate == 2) ? thu : tho;

    unsigned long long a0[3], a1[3];
#pragma unroll
    for (int p = 0; p < 3; p++) {
        float blo = __ldg(bg + 2 * p + 0) + __ldg(tg + 2 * p + 0);
        float bhi = __ldg(bg + 2 * p + 1) + __ldg(tg + 2 * p + 1);
        unsigned long long bp;
        asm("mov.b64 %0, {%1, %2};" : "=l"(bp) : "f"(blo), "f"(bhi));
        a0[p] = bp;
        a1[p] = bp;
    }

    const int cc = tid & 7;   // d-group for staging
    const int rr = tid >> 3;  // row for staging

    // prologue: prefetch X tile 0 into registers
    float4 xr0, xr1, xr2, xr3;
    {
        const float4* xb = reinterpret_cast<const float4*>(X) + cc;
        xr0 = __ldg(xb + (size_t)(rowbase + rr +  0) * (DD / 4));
        xr1 = __ldg(xb + (size_t)(rowbase + rr + 32) * (DD / 4));
        xr2 = __ldg(xb + (size_t)(rowbase + rr + 64) * (DD / 4));
        xr3 = __ldg(xb + (size_t)(rowbase + rr + 96) * (DD / 4));
    }

    for (int kh = 0; kh < 2; kh++) {
        __syncthreads();  // prior compute done before Wph overwrite
#pragma unroll
        for (int k = 0; k < 24; k++) {
            int idx = tid + (k << 8);          // dd*24 + col
            int dd  = idx / 24;
            int col = idx - dd * 24;
            int g2  = col / 6;
            int q2  = col - g2 * 6;
            const float* Ws = (g2 == 0) ? Wf : (g2 == 1) ? Wi : (g2 == 2) ? Wu : Wo;
            Wph[idx] = Ws[((kh << 8) + dd) * 6 + q2];
        }
        for (int tile = 0; tile < 8; tile++) {
            __syncthreads();  // Wph ready (tile 0) / Xsh free (prior compute done)
            // store the prefetched tile (transpose), data already in regs
            {
                const int c4 = cc << 2;
                Xsh[(c4 + 0) * 130 + rr +  0] = xr0.x;
                Xsh[(c4 + 1) * 130 + rr +  0] = xr0.y;
                Xsh[(c4 + 2) * 130 + rr +  0] = xr0.z;
                Xsh[(c4 + 3) * 130 + rr +  0] = xr0.w;
                Xsh[(c4 + 0) * 130 + rr + 32] = xr1.x;
                Xsh[(c4 + 1) * 130 + rr + 32] = xr1.y;
                Xsh[(c4 + 2) * 130 + rr + 32] = xr1.z;
                Xsh[(c4 + 3) * 130 + rr + 32] = xr1.w;
                Xsh[(c4 + 0) * 130 + rr + 64] = xr2.x;
                Xsh[(c4 + 1) * 130 + rr + 64] = xr2.y;
                Xsh[(c4 + 2) * 130 + rr + 64] = xr2.z;
                Xsh[(c4 + 3) * 130 + rr + 64] = xr2.w;
                Xsh[(c4 + 0) * 130 + rr + 96] = xr3.x;
                Xsh[(c4 + 1) * 130 + rr + 96] = xr3.y;
                Xsh[(c4 + 2) * 130 + rr + 96] = xr3.z;
                Xsh[(c4 + 3) * 130 + rr + 96] = xr3.w;
            }
            __syncthreads();  // Xsh ready

            // prefetch next tile's X (hidden behind this tile's compute)
            const int gtn = (kh << 3) + tile + 1;
            if (gtn < 16) {
                const float4* xb = reinterpret_cast<const float4*>(X) + (gtn << 3) + cc;
                xr0 = __ldg(xb + (size_t)(rowbase + rr +  0) * (DD / 4));
                xr1 = __ldg(xb + (size_t)(rowbase + rr + 32) * (DD / 4));
                xr2 = __ldg(xb + (size_t)(rowbase + rr + 64) * (DD / 4));
                xr3 = __ldg(xb + (size_t)(rowbase + rr + 96) * (DD / 4));
            }

#pragma unroll
            for (int d = 0; d < 32; d++) {
                const int dd = (tile << 5) + d;
                const unsigned long long* wp =
                    reinterpret_cast<const unsigned long long*>(&Wph[dd * 24 + gate * 6]);
                const unsigned long long w01 = wp[0];
                const unsigned long long w23 = wp[1];
                const unsigned long long w45 = wp[2];
                const float2 x2 = *reinterpret_cast<const float2*>(&Xsh[d * 130 + rloc]);
                unsigned long long xa, xb2;
                asm("mov.b64 %0, {%1, %1};" : "=l"(xa)  : "f"(x2.x));
                asm("mov.b64 %0, {%1, %1};" : "=l"(xb2) : "f"(x2.y));
                asm("fma.rn.f32x2 %0, %1, %2, %0;" : "+l"(a0[0]) : "l"(w01), "l"(xa));
                asm("fma.rn.f32x2 %0, %1, %2, %0;" : "+l"(a0[1]) : "l"(w23), "l"(xa));
                asm("fma.rn.f32x2 %0, %1, %2, %0;" : "+l"(a0[2]) : "l"(w45), "l"(xa));
                asm("fma.rn.f32x2 %0, %1, %2, %0;" : "+l"(a1[0]) : "l"(w01), "l"(xb2));
                asm("fma.rn.f32x2 %0, %1, %2, %0;" : "+l"(a1[1]) : "l"(w23), "l"(xb2));
                asm("fma.rn.f32x2 %0, %1, %2, %0;" : "+l"(a1[2]) : "l"(w45), "l"(xb2));
            }
        }
    }

    const int t = rowbase >> 8;
    const int b = (rowbase & 255) + rloc;       // even; b+1 shares b>>3
    float* dst = g_pre2 + ((size_t)((b >> 3) * 64 + t) * 192) + (b & 7) * 24 + gate * 6;
    unsigned long long* d64 = reinterpret_cast<unsigned long long*>(dst);
    d64[0] = a0[0]; d64[1] = a0[1]; d64[2] = a0[2];
    unsigned long long* e64 = reinterpret_cast<unsigned long long*>(dst + 24);
    e64[0] = a1[0]; e64[1] = a1[1]; e64[2] = a1[2];
}

// tanh via CF rational, one rcp; err <= ~2e-5 for |x| <= 2.2 (|c| <= 2.08).
__device__ __forceinline__ float tanh_rat(float x) {
    float s = x * x;
    float num = fmaf(s, fmaf(s, 21.0f, 1260.0f), 10395.0f);
    float den = fmaf(s, fmaf(s, s + 210.0f, 4725.0f), 10395.0f);
    float r;
    asm("rcp.approx.f32 %0, %1;" : "=f"(r) : "f"(den));
    return x * num * r;
}

// ---------------------------------------------------------------------------
// K2: LSTM scan — EXACT R11 kernel (best measured: 17.2us).
// Wire-split, 2 scan warps x 4 batches. lane = bl*8 + gate*2 + qh.
// ---------------------------------------------------------------------------
__global__ void __launch_bounds__(128, 1) k2_scan(
    const float* __restrict__ Wf, const float* __restrict__ Wi,
    const float* __restrict__ Wu, const float* __restrict__ Wo,
    float* __restrict__ out)
{
    __shared__ float ps[TT * 192];    // 48KB : [t][bloc(8)][gate][q]

    const int tid = threadIdx.x;

    {
        const float4* src = reinterpret_cast<const float4*>(g_pre2 + (size_t)blockIdx.x * (TT * 192));
        float4* dst = reinterpret_cast<float4*>(ps);
#pragma unroll
        for (int i = 0; i < (TT * 192) / 4 / 128; i++)
            dst[tid + i * 128] = src[tid + i * 128];
    }
    __syncthreads();
    if (tid >= 64) return;

    const int lane = tid & 31;
    const int wrp  = tid >> 5;            // 0 or 1
    const int qh   = lane & 1;            // wire half
    const int g    = (lane >> 1) & 3;     // gate
    const int bl   = lane >> 3;           // batch within warp (0..3)
    const int bloc = (wrp << 2) + bl;     // batch within block (0..7)
    const int b    = (blockIdx.x << 3) + bloc;
    const int q0   = 3 * qh;
    const float* Wg = (g == 0) ? Wf : (g == 1) ? Wi : (g == 2) ? Wu : Wo;

    float Whk[6][3];
#pragma unroll
    for (int k = 0; k < 6; k++)
#pragma unroll
        for (int j = 0; j < 3; j++)
            Whk[k][j] = __ldg(Wg + (DD + k) * 6 + q0 + j);

    float h6[6];
#pragma unroll
    for (int k = 0; k < 6; k++) h6[k] = 0.0f;
    float c[3] = { 0.0f, 0.0f, 0.0f };

    const float* pb = ps + bloc * 24 + g * 6 + q0;
    const unsigned mask = 0xffffffffu;
    const int lb  = (lane & 24) | qh;     // gate-0 lane of this (batch, qh)
    const bool isU = (g == 2);
    const float cmul = isU ? -2.0f : -1.0f;
    const bool store = (g == 0);

#pragma unroll 2
    for (int t = 0; t < TT; t++) {
        const float p0 = pb[t * 192 + 0];
        const float p1 = pb[t * 192 + 1];
        const float p2 = pb[t * 192 + 2];

        float a[3];
        {
            float pj[3] = { p0, p1, p2 };
#pragma unroll
            for (int j = 0; j < 3; j++) {
                float u0 = fmaf(h6[0], Whk[0][j], fmaf(h6[1], Whk[1][j], fmaf(h6[2], Whk[2][j], pj[j])));
                float u1 = fmaf(h6[3], Whk[3][j], fmaf(h6[4], Whk[4][j], h6[5] * Whk[5][j]));
                a[j] = u0 + u1;
            }
        }

        float z0 = __cosf(a[0]);
        float z1 = __cosf(a[1]);
        float z2 = __cosf(a[2]);

        float zp0 = __shfl_xor_sync(mask, z0, 1);
        float zp1 = __shfl_xor_sync(mask, z1, 1);
        float zp2 = __shfl_xor_sync(mask, z2, 1);
        float zA0 = qh ? zp0 : z0;   // q0
        float zA1 = qh ? zp1 : z1;   // q1
        float zA2 = qh ? zp2 : z2;   // q2
        float zB0 = qh ? z0 : zp0;   // q3
        float zB1 = qh ? z1 : zp1;   // q4
        float zB2 = qh ? z2 : zp2;   // q5

        float z01 = zA0 * zA1;
        float z23 = zA2 * zB0;
        float z45 = zB1 * zB2;
        float w3  = z01 * z23;
        float wv0 = qh ? w3        : zA1 * (z23 * z45);   // w3 : w0
        float wv1 = qh ? w3 * zB1  : z01;                 // w4 : w1
        float wv2 = qh ? w3 * z45  : z01 * zA2;           // w5 : w2

        float v0, v1, v2;
        {
            float e0 = __expf(cmul * wv0);
            float e1 = __expf(cmul * wv1);
            float e2 = __expf(cmul * wv2);
            float s0 = __fdividef(1.0f, 1.0f + e0);
            float s1 = __fdividef(1.0f, 1.0f + e1);
            float s2 = __fdividef(1.0f, 1.0f + e2);
            v0 = isU ? fmaf(2.0f, s0, -1.0f) : s0;
            v1 = isU ? fmaf(2.0f, s1, -1.0f) : s1;
            v2 = isU ? fmaf(2.0f, s2, -1.0f) : s2;
        }

        float hq[3];
#pragma unroll
        for (int j = 0; j < 3; j++) {
            float vj = (j == 0) ? v0 : (j == 1) ? v1 : v2;
            float fq = __shfl_sync(mask, vj, lb + 0);
            float iq = __shfl_sync(mask, vj, lb + 2);
            float uq = __shfl_sync(mask, vj, lb + 4);
            float oq = __shfl_sync(mask, vj, lb + 6);
            float cn = fmaf(fq, c[j], iq * uq);
            c[j] = cn;
            hq[j] = oq * tanh_rat(cn);     // |cn| <= 2.08 guaranteed
        }

        if (store) {
            float* o0 = out + ((size_t)t * BB + b) * 6 + q0;
            o0[0] = hq[0]; o0[1] = hq[1]; o0[2] = hq[2];
        }

        float hp0 = __shfl_xor_sync(mask, hq[0], 1);
        float hp1 = __shfl_xor_sync(mask, hq[1], 1);
        float hp2 = __shfl_xor_sync(mask, hq[2], 1);
        h6[0] = qh ? hp0 : hq[0];
        h6[1] = qh ? hp1 : hq[1];
        h6[2] = qh ? hp2 : hq[2];
        h6[3] = qh ? hq[0] : hp0;
        h6[4] = qh ? hq[1] : hp1;
        h6[5] = qh ? hq[2] : hp2;
    }

    if (store) {
        float* hx = out + (size_t)TT * BB * 6 + (size_t)b * 6 + q0;
        float* cx = hx + BB * 6;
        hx[0] = qh ? h6[3] : h6[0];
        hx[1] = qh ? h6[4] : h6[1];
        hx[2] = qh ? h6[5] : h6[2];
        cx[0] = c[0]; cx[1] = c[1]; cx[2] = c[2];
    }
}

extern "C" void kernel_launch(void* const* d_in, const int* in_sizes, int n_in,
                              void* d_out, int out_size)
{
    const float* X   = (const float*)d_in[0];
    const float* Wf  = (const float*)d_in[1];
    const float* bf  = (const float*)d_in[2];
    const float* Wi  = (const float*)d_in[3];
    const float* bi  = (const float*)d_in[4];
    const float* Wu  = (const float*)d_in[5];
    const float* bu  = (const float*)d_in[6];
    const float* Wo  = (const float*)d_in[7];
    const float* bo  = (const float*)d_in[8];
    const float* thf = (const float*)d_in[9];
    const float* thi = (const float*)d_in[10];
    const float* thu = (const float*)d_in[11];
    const float* tho = (const float*)d_in[12];
    float* out = (float*)d_out;

    k1_gemm<<<128, 256>>>(X, Wf, bf, Wi, bi, Wu, bu, Wo, bo, thf, thi, thu, tho);
    k2_scan<<<32, 128>>>(Wf, Wi, Wu, Wo, out);
}